// round 2
// baseline (speedup 1.0000x reference)
#include <cuda_runtime.h>

// Problem constants (shapes fixed by the reference)
#define NHEADS  20
#define NUM_EX  13
#define PAD     12   // pad 10-float rows to 12 for 16B-aligned vector LDS

// Folded-weight buffer layout (float offsets)
#define OFF_E    0                      // E'  : 20*13*12 = 3120  (b1 + emb@W1e + bf@W1f folded in)
#define OFF_W1F  3120                   // W1f : 20*3*12  = 720
#define OFF_W2   3840                   // W2  : 20*12    = 240
#define OFF_B2   4080                   // b2  : 20
#define OFF_WO   4100                   // Wo  : 20
#define OFF_BO   4120                   // bo  : 1
#define PREP_N   4121

__device__ float g_prep[4128];

// ---------------------------------------------------------------------------
// Prep: fold Wf/bf/emb/b1 into lookup tables. Tiny, runs once per launch.
// E'[h][idx][j] = b1[h][j] + sum_c emb[idx][c]*W1[h][c][j] + sum_i bf[i]*W1[h][3+i][j]
// W1f[h][c][j]  = sum_i Wf[c][i]*W1[h][3+i][j]
// ---------------------------------------------------------------------------
__global__ void prep_kernel(const float* __restrict__ emb, const float* __restrict__ Wf,
                            const float* __restrict__ bf,  const float* __restrict__ W1,
                            const float* __restrict__ b1,  const float* __restrict__ W2,
                            const float* __restrict__ b2,  const float* __restrict__ Wo,
                            const float* __restrict__ bo) {
    int t = blockIdx.x * blockDim.x + threadIdx.x;
    if (t >= PREP_N) return;
    float v = 0.0f;
    if (t < OFF_W1F) {
        int j = t % PAD; int r = t / PAD; int idx = r % NUM_EX; int h = r / NUM_EX;
        if (j < 10) {
            v = b1[h * 10 + j];
            #pragma unroll
            for (int c = 0; c < 3; c++) v += emb[idx * 3 + c] * W1[(h * 8 + c) * 10 + j];
            #pragma unroll
            for (int i = 0; i < 5; i++) v += bf[i] * W1[(h * 8 + 3 + i) * 10 + j];
        }
    } else if (t < OFF_W2) {
        int u = t - OFF_W1F; int j = u % PAD; int r = u / PAD; int c = r % 3; int h = r / 3;
        if (j < 10) {
            #pragma unroll
            for (int i = 0; i < 5; i++) v += Wf[c * 5 + i] * W1[(h * 8 + 3 + i) * 10 + j];
        }
    } else if (t < OFF_B2) {
        int u = t - OFF_W2; int j = u % PAD; int h = u / PAD;
        if (j < 10) v = W2[h * 10 + j];
    } else if (t < OFF_WO) {
        v = b2[t - OFF_B2];
    } else if (t < OFF_BO) {
        v = Wo[t - OFF_WO];
    } else {
        v = bo[0];
    }
    g_prep[t] = v;
}

// ---------------------------------------------------------------------------
// Main kernel: 1 sample/thread, folded weights in smem (broadcast LDS),
// f/e consumed in 4-head groups via float4/int4 to bound registers.
// ---------------------------------------------------------------------------
__global__ __launch_bounds__(256) void airfit_kernel(const int* __restrict__ e,
                                                     const float* __restrict__ f,
                                                     float* __restrict__ out, int B) {
    __shared__ __align__(16) float sp[4128];
    for (int i = threadIdx.x; i < PREP_N; i += 256) sp[i] = g_prep[i];
    __syncthreads();

    int s = blockIdx.x * 256 + threadIdx.x;
    if (s >= B) return;

    const float4* f4 = reinterpret_cast<const float4*>(f) + (size_t)s * 15;  // 60 floats/row
    const int4*   e4 = reinterpret_cast<const int4*>(e)  + (size_t)s * 5;    // 20 ints/row

    float res = sp[OFF_BO];

    #pragma unroll
    for (int hg = 0; hg < 5; hg++) {               // 5 groups of 4 heads
        float4 fA = f4[hg * 3 + 0];
        float4 fB = f4[hg * 3 + 1];
        float4 fC = f4[hg * 3 + 2];
        int4   ev = e4[hg];
        float g[12] = {fA.x, fA.y, fA.z, fA.w, fB.x, fB.y, fB.z, fB.w,
                       fC.x, fC.y, fC.z, fC.w};
        int idx[4] = {ev.x, ev.y, ev.z, ev.w};

        #pragma unroll
        for (int k = 0; k < 4; k++) {
            int h = hg * 4 + k;

            // accumulator init = E'[h][e] row (biases + embedding contribution folded)
            const float* Er = &sp[OFF_E + (h * NUM_EX + idx[k]) * PAD];
            float4 A0 = *reinterpret_cast<const float4*>(Er);
            float4 A1 = *reinterpret_cast<const float4*>(Er + 4);
            float2 A2 = *reinterpret_cast<const float2*>(Er + 8);
            float a[10] = {A0.x, A0.y, A0.z, A0.w, A1.x, A1.y, A1.z, A1.w, A2.x, A2.y};

            // + f(3) @ W1f(3x10)
            #pragma unroll
            for (int c = 0; c < 3; c++) {
                const float* wr = &sp[OFF_W1F + (h * 3 + c) * PAD];
                float4 W0 = *reinterpret_cast<const float4*>(wr);
                float4 W1v = *reinterpret_cast<const float4*>(wr + 4);
                float2 W2v = *reinterpret_cast<const float2*>(wr + 8);
                float w[10] = {W0.x, W0.y, W0.z, W0.w, W1v.x, W1v.y, W1v.z, W1v.w, W2v.x, W2v.y};
                float fv = g[k * 3 + c];
                #pragma unroll
                for (int j = 0; j < 10; j++) a[j] = fmaf(fv, w[j], a[j]);
            }

            // leaky_relu (slope 0.01) then dot with W2[h], + b2[h]
            const float* ur = &sp[OFF_W2 + h * PAD];
            float4 U0 = *reinterpret_cast<const float4*>(ur);
            float4 U1 = *reinterpret_cast<const float4*>(ur + 4);
            float2 U2 = *reinterpret_cast<const float2*>(ur + 8);
            float w2[10] = {U0.x, U0.y, U0.z, U0.w, U1.x, U1.y, U1.z, U1.w, U2.x, U2.y};
            float d = sp[OFF_B2 + h];
            #pragma unroll
            for (int j = 0; j < 10; j++) {
                float t = fmaxf(a[j], 0.0f) + 0.01f * fminf(a[j], 0.0f);
                d = fmaf(t, w2[j], d);
            }

            // softplus(d) = max(d,0) + log(1 + exp(-|d|))   (stable, matches logaddexp(d,0))
            float m  = fmaxf(d, 0.0f);
            float z  = __expf(-fabsf(d));
            float spv = m + __logf(1.0f + z);

            res = fmaf(spv, sp[OFF_WO + h], res);
        }
    }
    out[s] = res;
}

// ---------------------------------------------------------------------------
extern "C" void kernel_launch(void* const* d_in, const int* in_sizes, int n_in,
                              void* d_out, int out_size) {
    const int*   e   = (const int*)  d_in[0];
    const float* f   = (const float*)d_in[1];
    const float* emb = (const float*)d_in[2];
    const float* Wf  = (const float*)d_in[3];
    const float* bf  = (const float*)d_in[4];
    const float* W1  = (const float*)d_in[5];
    const float* b1  = (const float*)d_in[6];
    const float* W2  = (const float*)d_in[7];
    const float* b2  = (const float*)d_in[8];
    const float* Wo  = (const float*)d_in[9];
    const float* bo  = (const float*)d_in[10];
    float* out = (float*)d_out;
    int B = out_size;  // output is (B, 1) float32

    prep_kernel<<<(PREP_N + 255) / 256, 256>>>(emb, Wf, bf, W1, b1, W2, b2, Wo, bo);
    airfit_kernel<<<(B + 255) / 256, 256>>>(e, f, out, B);
}